// round 1
// baseline (speedup 1.0000x reference)
#include <cuda_runtime.h>
#include <math.h>

// ---------------- problem constants ----------------
#define NTOK   8192          // B*S = 16*512
#define EDIM   1024
#define NHEAD  16
#define HDIM   64
#define NST    6
#define NROWS  (NST*NTOK)    // 49152
#define HIDD   1024
#define LN_EPS 1e-5f

// ---------------- scratch (device globals; no allocs allowed) ----------------
__device__ float g_Q[(size_t)NROWS * EDIM];
__device__ float g_K[(size_t)NROWS * EDIM];
__device__ float g_V[(size_t)NROWS * EDIM];
__device__ float g_CTX[(size_t)NROWS * EDIM];
__device__ float g_ATT[(size_t)NROWS * EDIM];
__device__ float g_FUSED[(size_t)NTOK * EDIM];

// ---------------- SGEMM: C[M,Nc] = A[M,K] @ B[Nc,K]^T + bias[Nc] ----------------
// A row-major MxK, B row-major NcxK (both K-contiguous -> "NT" GEMM).
// 128x128 tile, BK=16, 256 threads, 8x8 per thread.
#define BM 128
#define BN 128
#define BKK 16

__global__ __launch_bounds__(256, 2)
void sgemm_nt_bias(const float* __restrict__ A, const float* __restrict__ Bw,
                   const float* __restrict__ bias, float* __restrict__ C,
                   int M, int Nc, int Kd)
{
    __shared__ float As[BKK][BM];
    __shared__ float Bs[BKK][BN];

    const int tid = threadIdx.x;
    const int bm = blockIdx.y * BM;
    const int bn = blockIdx.x * BN;

    const int lrow = tid >> 2;          // 0..63
    const int lc4  = (tid & 3) << 2;    // 0,4,8,12

    const int trow = (tid >> 4) << 3;   // 0..120 step 8
    const int tcol = (tid & 15) << 3;

    float acc[8][8];
    #pragma unroll
    for (int i = 0; i < 8; i++)
        #pragma unroll
        for (int j = 0; j < 8; j++) acc[i][j] = 0.f;

    const float* Ab = A  + (size_t)bm * Kd;
    const float* Bb = Bw + (size_t)bn * Kd;

    for (int k0 = 0; k0 < Kd; k0 += BKK) {
        #pragma unroll
        for (int r = 0; r < 2; r++) {
            int row = lrow + r * 64;
            float4 va = *reinterpret_cast<const float4*>(Ab + (size_t)row * Kd + k0 + lc4);
            As[lc4 + 0][row] = va.x; As[lc4 + 1][row] = va.y;
            As[lc4 + 2][row] = va.z; As[lc4 + 3][row] = va.w;
            float4 vb = *reinterpret_cast<const float4*>(Bb + (size_t)row * Kd + k0 + lc4);
            Bs[lc4 + 0][row] = vb.x; Bs[lc4 + 1][row] = vb.y;
            Bs[lc4 + 2][row] = vb.z; Bs[lc4 + 3][row] = vb.w;
        }
        __syncthreads();

        #pragma unroll
        for (int kk = 0; kk < BKK; kk++) {
            float a[8], b[8];
            float4 a0 = *reinterpret_cast<const float4*>(&As[kk][trow]);
            float4 a1 = *reinterpret_cast<const float4*>(&As[kk][trow + 4]);
            float4 b0 = *reinterpret_cast<const float4*>(&Bs[kk][tcol]);
            float4 b1 = *reinterpret_cast<const float4*>(&Bs[kk][tcol + 4]);
            a[0]=a0.x; a[1]=a0.y; a[2]=a0.z; a[3]=a0.w;
            a[4]=a1.x; a[5]=a1.y; a[6]=a1.z; a[7]=a1.w;
            b[0]=b0.x; b[1]=b0.y; b[2]=b0.z; b[3]=b0.w;
            b[4]=b1.x; b[5]=b1.y; b[6]=b1.z; b[7]=b1.w;
            #pragma unroll
            for (int i = 0; i < 8; i++)
                #pragma unroll
                for (int j = 0; j < 8; j++)
                    acc[i][j] += a[i] * b[j];
        }
        __syncthreads();
    }

    #pragma unroll
    for (int i = 0; i < 8; i++) {
        size_t crow = (size_t)(bm + trow + i) * Nc + bn + tcol;
        #pragma unroll
        for (int j = 0; j < 8; j += 4) {
            float4 o;
            o.x = acc[i][j + 0] + bias[bn + tcol + j + 0];
            o.y = acc[i][j + 1] + bias[bn + tcol + j + 1];
            o.z = acc[i][j + 2] + bias[bn + tcol + j + 2];
            o.w = acc[i][j + 3] + bias[bn + tcol + j + 3];
            *reinterpret_cast<float4*>(&C[crow + j]) = o;
        }
    }
}

// ---------------- tiny 6x6 attention per (token, head) ----------------
// One block per token, 8 warps; 2 passes of 8 heads (smem = 3*6*512 floats = 36KB).
__global__ __launch_bounds__(256)
void attn_kernel(const float* __restrict__ Q, const float* __restrict__ Kb,
                 const float* __restrict__ V, float* __restrict__ CTX)
{
    const int n    = blockIdx.x;
    const int tid  = threadIdx.x;
    const int warp = tid >> 5;
    const int lane = tid & 31;

    __shared__ float sq[NST][512];
    __shared__ float sk[NST][512];
    __shared__ float sv[NST][512];
    __shared__ float ssc[8][40];

    for (int pass = 0; pass < 2; pass++) {
        const int coff = pass * 512;          // column offset into E
        __syncthreads();                       // protect smem reuse across passes
        for (int idx = tid; idx < NST * 512; idx += 256) {
            int j = idx >> 9, e = idx & 511;
            size_t g = ((size_t)j * NTOK + n) * EDIM + coff + e;
            sq[j][e] = Q[g];
            sk[j][e] = Kb[g];
            sv[j][e] = V[g];
        }
        __syncthreads();

        const int h  = pass * 8 + warp;        // global head
        const int lc = warp * HDIM;            // column base in smem slice

        // scores (36 pairs, scaled by 1/sqrt(64)=0.125)
        for (int p = lane; p < 36; p += 32) {
            int qi = p / 6, ki = p % 6;
            float s = 0.f;
            #pragma unroll
            for (int d = 0; d < HDIM; d++)
                s += sq[qi][lc + d] * sk[ki][lc + d];
            ssc[warp][p] = s * 0.125f;
        }
        __syncwarp();

        // softmax over k (row-wise, 6 rows handled by lanes 0..5)
        if (lane < 6) {
            float row[6], m = -1e30f;
            #pragma unroll
            for (int kk = 0; kk < 6; kk++) { row[kk] = ssc[warp][lane * 6 + kk]; m = fmaxf(m, row[kk]); }
            float s = 0.f;
            #pragma unroll
            for (int kk = 0; kk < 6; kk++) { row[kk] = __expf(row[kk] - m); s += row[kk]; }
            float inv = 1.f / s;
            #pragma unroll
            for (int kk = 0; kk < 6; kk++) ssc[warp][lane * 6 + kk] = row[kk] * inv;
        }
        __syncwarp();

        // ctx = attn @ v, write to CTX row (qi*NTOK + n)
        for (int o = lane; o < NST * HDIM; o += 32) {
            int qi = o >> 6, d = o & 63;
            float c = 0.f;
            #pragma unroll
            for (int kk = 0; kk < 6; kk++)
                c += ssc[warp][qi * 6 + kk] * sv[kk][lc + d];
            CTX[((size_t)qi * NTOK + n) * EDIM + h * HDIM + d] = c;
        }
    }
}

// ---------------- block reduction helper (256 threads) ----------------
__device__ __forceinline__ float block_sum(float v, float* sbuf)
{
    const int lane = threadIdx.x & 31;
    const int wid  = threadIdx.x >> 5;
    #pragma unroll
    for (int o = 16; o > 0; o >>= 1) v += __shfl_xor_sync(0xffffffffu, v, o);
    if (lane == 0) sbuf[wid] = v;
    __syncthreads();
    if (wid == 0) {
        float r = (lane < 8) ? sbuf[lane] : 0.f;
        #pragma unroll
        for (int o = 4; o > 0; o >>= 1) r += __shfl_xor_sync(0xffffffffu, r, o);
        if (lane == 0) sbuf[0] = r;
    }
    __syncthreads();
    float r = sbuf[0];
    __syncthreads();   // allow sbuf reuse by next call
    return r;
}

// ---------------- residual + LN1 + softmax(fusion_w)-weighted sum ----------------
__global__ __launch_bounds__(256)
void ln1_fuse_kernel(const float* __restrict__ ATT, const float* __restrict__ ST,
                     const float* __restrict__ g1, const float* __restrict__ b1,
                     const float* __restrict__ fw, float* __restrict__ FUSED)
{
    __shared__ float sbuf[32];
    const int n = blockIdx.x, tid = threadIdx.x;

    float w[6];
    {
        float m = -1e30f;
        #pragma unroll
        for (int j = 0; j < 6; j++) { w[j] = fw[j]; m = fmaxf(m, w[j]); }
        float s = 0.f;
        #pragma unroll
        for (int j = 0; j < 6; j++) { w[j] = __expf(w[j] - m); s += w[j]; }
        float inv = 1.f / s;
        #pragma unroll
        for (int j = 0; j < 6; j++) w[j] *= inv;
    }

    float accv[4] = {0.f, 0.f, 0.f, 0.f};
    for (int j = 0; j < 6; j++) {
        size_t base = ((size_t)j * NTOK + n) * EDIM;
        float x[4], lsum = 0.f;
        #pragma unroll
        for (int t = 0; t < 4; t++) {
            int e = t * 256 + tid;
            x[t] = ATT[base + e] + ST[base + e];
            lsum += x[t];
        }
        float mean = block_sum(lsum, sbuf) * (1.f / EDIM);
        float lvar = 0.f;
        #pragma unroll
        for (int t = 0; t < 4; t++) { float d = x[t] - mean; lvar += d * d; }
        float var = block_sum(lvar, sbuf) * (1.f / EDIM);
        float inv = rsqrtf(var + LN_EPS);
        #pragma unroll
        for (int t = 0; t < 4; t++) {
            int e = t * 256 + tid;
            accv[t] += w[j] * ((x[t] - mean) * inv * g1[e] + b1[e]);
        }
    }
    #pragma unroll
    for (int t = 0; t < 4; t++)
        FUSED[(size_t)n * EDIM + t * 256 + tid] = accv[t];
}

// ---------------- LeakyReLU + LN2 (in-place on d_out) ----------------
__global__ __launch_bounds__(256)
void lrelu_ln2_kernel(float* __restrict__ O, const float* __restrict__ g2,
                      const float* __restrict__ b2)
{
    __shared__ float sbuf[32];
    const int n = blockIdx.x, tid = threadIdx.x;
    size_t base = (size_t)n * HIDD;

    float x[4], lsum = 0.f;
    #pragma unroll
    for (int t = 0; t < 4; t++) {
        int e = t * 256 + tid;
        float v = O[base + e];
        v = (v >= 0.f) ? v : 0.01f * v;
        x[t] = v; lsum += v;
    }
    float mean = block_sum(lsum, sbuf) * (1.f / HIDD);
    float lvar = 0.f;
    #pragma unroll
    for (int t = 0; t < 4; t++) { float d = x[t] - mean; lvar += d * d; }
    float var = block_sum(lvar, sbuf) * (1.f / HIDD);
    float inv = rsqrtf(var + LN_EPS);
    #pragma unroll
    for (int t = 0; t < 4; t++) {
        int e = t * 256 + tid;
        O[base + e] = (x[t] - mean) * inv * g2[e] + b2[e];
    }
}

// ---------------- launch ----------------
extern "C" void kernel_launch(void* const* d_in, const int* in_sizes, int n_in,
                              void* d_out, int out_size)
{
    const float* st = (const float*)d_in[0];   // (6,B,S,E) == (NROWS, E), row r = j*NTOK + n
    const float* Wq = (const float*)d_in[1];  const float* bq = (const float*)d_in[2];
    const float* Wk = (const float*)d_in[3];  const float* bk = (const float*)d_in[4];
    const float* Wv = (const float*)d_in[5];  const float* bv = (const float*)d_in[6];
    const float* Wo = (const float*)d_in[7];  const float* bo = (const float*)d_in[8];
    const float* g1 = (const float*)d_in[9];  const float* b1 = (const float*)d_in[10];
    const float* fw = (const float*)d_in[11];
    const float* Wf = (const float*)d_in[12]; const float* bf = (const float*)d_in[13];
    const float* g2 = (const float*)d_in[14]; const float* b2 = (const float*)d_in[15];
    float* out = (float*)d_out;

    float *Qb, *Kb, *Vb, *CTXb, *ATTb, *FUSb;
    cudaGetSymbolAddress((void**)&Qb,   g_Q);
    cudaGetSymbolAddress((void**)&Kb,   g_K);
    cudaGetSymbolAddress((void**)&Vb,   g_V);
    cudaGetSymbolAddress((void**)&CTXb, g_CTX);
    cudaGetSymbolAddress((void**)&ATTb, g_ATT);
    cudaGetSymbolAddress((void**)&FUSb, g_FUSED);

    dim3 blk(256);
    dim3 gproj(EDIM / BN, NROWS / BM);   // (8, 384)
    sgemm_nt_bias<<<gproj, blk>>>(st, Wq, bq, Qb, NROWS, EDIM, EDIM);
    sgemm_nt_bias<<<gproj, blk>>>(st, Wk, bk, Kb, NROWS, EDIM, EDIM);
    sgemm_nt_bias<<<gproj, blk>>>(st, Wv, bv, Vb, NROWS, EDIM, EDIM);

    attn_kernel<<<NTOK, 256>>>(Qb, Kb, Vb, CTXb);

    sgemm_nt_bias<<<gproj, blk>>>(CTXb, Wo, bo, ATTb, NROWS, EDIM, EDIM);

    ln1_fuse_kernel<<<NTOK, 256>>>(ATTb, st, g1, b1, fw, FUSb);

    dim3 gmlp(HIDD / BN, NTOK / BM);     // (8, 64)
    sgemm_nt_bias<<<gmlp, blk>>>(FUSb, Wf, bf, out, NTOK, HIDD, EDIM);

    lrelu_ln2_kernel<<<NTOK, 256>>>(out, g2, b2);
}

// round 2
// speedup vs baseline: 2.4609x; 2.4609x over previous
#include <cuda_runtime.h>
#include <math.h>

// ---------------- problem constants ----------------
#define NTOK   8192          // B*S = 16*512
#define EDIM   1024
#define NHEAD  16
#define HDIM   64
#define NST    6
#define NROWS  (NST*NTOK)    // 49152
#define HIDD   1024
#define LN_EPS 1e-5f

// ---------------- scratch (device globals; no allocs allowed) ----------------
__device__ float g_Q[(size_t)NROWS * EDIM];
__device__ float g_K[(size_t)NROWS * EDIM];
__device__ float g_V[(size_t)NROWS * EDIM];
__device__ float g_CTX[(size_t)NROWS * EDIM];
__device__ float g_ATT[(size_t)NROWS * EDIM];
__device__ float g_FUSED[(size_t)NTOK * EDIM];

// ---------------- TF32 helpers ----------------
__device__ __forceinline__ unsigned f2tf32(float f) {
    unsigned u;
    asm("cvt.rna.tf32.f32 %0, %1;" : "=r"(u) : "f"(f));
    return u;
}

__device__ __forceinline__ void mma_tf32(float* c, const unsigned* a, const unsigned* b) {
    asm volatile(
        "mma.sync.aligned.m16n8k8.row.col.f32.tf32.tf32.f32 "
        "{%0,%1,%2,%3}, {%4,%5,%6,%7}, {%8,%9}, {%0,%1,%2,%3};"
        : "+f"(c[0]), "+f"(c[1]), "+f"(c[2]), "+f"(c[3])
        : "r"(a[0]), "r"(a[1]), "r"(a[2]), "r"(a[3]), "r"(b[0]), "r"(b[1]));
}

// ---------------- TF32 tensor-core GEMM ----------------
// C[M,Nc] = A[M,K] @ B[Nc,K]^T + bias[Nc]
// Block 128x128, BK=16, 256 threads = 8 warps (2x4), warp tile 64x32.
#define BK 16
#define SPAD 4
#define SSTR (BK + SPAD)   // 20

__global__ __launch_bounds__(256)
void gemm_tf32(const float* __restrict__ A, const float* __restrict__ Bw,
               const float* __restrict__ bias, float* __restrict__ C,
               int M, int Nc, int Kd)
{
    const int tid  = threadIdx.x;
    const int warp = tid >> 5;
    const int lane = tid & 31;
    const int g    = lane >> 2;     // group 0..7
    const int t    = lane & 3;      // thread-in-group 0..3

    const int bm = blockIdx.y * 128;
    const int bn = blockIdx.x * 128;
    const int wm = (warp >> 2) * 64;    // warp m offset within block
    const int wn = (warp & 3) * 32;     // warp n offset within block

    __shared__ unsigned As[128][SSTR];
    __shared__ unsigned Bs[128][SSTR];

    float acc[4][4][4];
    #pragma unroll
    for (int mt = 0; mt < 4; mt++)
        #pragma unroll
        for (int nt = 0; nt < 4; nt++)
            #pragma unroll
            for (int r = 0; r < 4; r++) acc[mt][nt][r] = 0.f;

    // global->smem mapping: 128x16 tile, each thread 2 float4 per matrix
    const int lr = tid >> 2;            // 0..63
    const int lc = (tid & 3) << 2;      // 0,4,8,12
    const float* Ag  = A  + (size_t)(bm + lr) * Kd + lc;
    const float* Ag2 = Ag + (size_t)64 * Kd;
    const float* Bg  = Bw + (size_t)(bn + lr) * Kd + lc;
    const float* Bg2 = Bg + (size_t)64 * Kd;

    float4 pa0 = *reinterpret_cast<const float4*>(Ag);
    float4 pa1 = *reinterpret_cast<const float4*>(Ag2);
    float4 pb0 = *reinterpret_cast<const float4*>(Bg);
    float4 pb1 = *reinterpret_cast<const float4*>(Bg2);

    const int niter = Kd / BK;
    for (int kt = 0; kt < niter; kt++) {
        __syncthreads();   // everyone done computing previous tile
        As[lr     ][lc+0] = f2tf32(pa0.x); As[lr     ][lc+1] = f2tf32(pa0.y);
        As[lr     ][lc+2] = f2tf32(pa0.z); As[lr     ][lc+3] = f2tf32(pa0.w);
        As[lr + 64][lc+0] = f2tf32(pa1.x); As[lr + 64][lc+1] = f2tf32(pa1.y);
        As[lr + 64][lc+2] = f2tf32(pa1.z); As[lr + 64][lc+3] = f2tf32(pa1.w);
        Bs[lr     ][lc+0] = f2tf32(pb0.x); Bs[lr     ][lc+1] = f2tf32(pb0.y);
        Bs[lr     ][lc+2] = f2tf32(pb0.z); Bs[lr     ][lc+3] = f2tf32(pb0.w);
        Bs[lr + 64][lc+0] = f2tf32(pb1.x); Bs[lr + 64][lc+1] = f2tf32(pb1.y);
        Bs[lr + 64][lc+2] = f2tf32(pb1.z); Bs[lr + 64][lc+3] = f2tf32(pb1.w);
        __syncthreads();

        if (kt + 1 < niter) {
            int off = (kt + 1) * BK;
            pa0 = *reinterpret_cast<const float4*>(Ag  + off);
            pa1 = *reinterpret_cast<const float4*>(Ag2 + off);
            pb0 = *reinterpret_cast<const float4*>(Bg  + off);
            pb1 = *reinterpret_cast<const float4*>(Bg2 + off);
        }

        #pragma unroll
        for (int kk = 0; kk < BK; kk += 8) {
            unsigned a[4][4], b[4][2];
            #pragma unroll
            for (int mt = 0; mt < 4; mt++) {
                int rb = wm + mt * 16;
                a[mt][0] = As[rb + g    ][kk + t    ];
                a[mt][1] = As[rb + g + 8][kk + t    ];
                a[mt][2] = As[rb + g    ][kk + t + 4];
                a[mt][3] = As[rb + g + 8][kk + t + 4];
            }
            #pragma unroll
            for (int nt = 0; nt < 4; nt++) {
                int nb = wn + nt * 8;
                b[nt][0] = Bs[nb + g][kk + t    ];
                b[nt][1] = Bs[nb + g][kk + t + 4];
            }
            #pragma unroll
            for (int mt = 0; mt < 4; mt++)
                #pragma unroll
                for (int nt = 0; nt < 4; nt++)
                    mma_tf32(acc[mt][nt], a[mt], b[nt]);
        }
    }

    // epilogue: bias + store
    #pragma unroll
    for (int mt = 0; mt < 4; mt++) {
        int r = bm + wm + mt * 16 + g;
        #pragma unroll
        for (int nt = 0; nt < 4; nt++) {
            int cc = bn + wn + nt * 8 + 2 * t;
            float bi0 = bias[cc], bi1 = bias[cc + 1];
            float2 o0 = make_float2(acc[mt][nt][0] + bi0, acc[mt][nt][1] + bi1);
            float2 o1 = make_float2(acc[mt][nt][2] + bi0, acc[mt][nt][3] + bi1);
            *reinterpret_cast<float2*>(&C[(size_t)r * Nc + cc])       = o0;
            *reinterpret_cast<float2*>(&C[(size_t)(r + 8) * Nc + cc]) = o1;
        }
    }
}

// ---------------- tiny 6x6 attention per (token, head) ----------------
__global__ __launch_bounds__(256)
void attn_kernel(const float* __restrict__ Q, const float* __restrict__ Kb,
                 const float* __restrict__ V, float* __restrict__ CTX)
{
    const int n    = blockIdx.x;
    const int tid  = threadIdx.x;
    const int warp = tid >> 5;
    const int lane = tid & 31;

    __shared__ float sq[NST][512];
    __shared__ float sk[NST][512];
    __shared__ float sv[NST][512];
    __shared__ float ssc[8][40];

    for (int pass = 0; pass < 2; pass++) {
        const int coff = pass * 512;
        __syncthreads();
        for (int idx = tid; idx < NST * 512; idx += 256) {
            int j = idx >> 9, e = idx & 511;
            size_t gofs = ((size_t)j * NTOK + n) * EDIM + coff + e;
            sq[j][e] = Q[gofs];
            sk[j][e] = Kb[gofs];
            sv[j][e] = V[gofs];
        }
        __syncthreads();

        const int h  = pass * 8 + warp;
        const int lc = warp * HDIM;

        for (int p = lane; p < 36; p += 32) {
            int qi = p / 6, ki = p % 6;
            float s = 0.f;
            #pragma unroll
            for (int d = 0; d < HDIM; d++)
                s += sq[qi][lc + d] * sk[ki][lc + d];
            ssc[warp][p] = s * 0.125f;
        }
        __syncwarp();

        if (lane < 6) {
            float row[6], m = -1e30f;
            #pragma unroll
            for (int kk = 0; kk < 6; kk++) { row[kk] = ssc[warp][lane * 6 + kk]; m = fmaxf(m, row[kk]); }
            float s = 0.f;
            #pragma unroll
            for (int kk = 0; kk < 6; kk++) { row[kk] = __expf(row[kk] - m); s += row[kk]; }
            float inv = 1.f / s;
            #pragma unroll
            for (int kk = 0; kk < 6; kk++) ssc[warp][lane * 6 + kk] = row[kk] * inv;
        }
        __syncwarp();

        for (int o = lane; o < NST * HDIM; o += 32) {
            int qi = o >> 6, d = o & 63;
            float c = 0.f;
            #pragma unroll
            for (int kk = 0; kk < 6; kk++)
                c += ssc[warp][qi * 6 + kk] * sv[kk][lc + d];
            CTX[((size_t)qi * NTOK + n) * EDIM + h * HDIM + d] = c;
        }
    }
}

// ---------------- block reduction helper (256 threads) ----------------
__device__ __forceinline__ float block_sum(float v, float* sbuf)
{
    const int lane = threadIdx.x & 31;
    const int wid  = threadIdx.x >> 5;
    #pragma unroll
    for (int o = 16; o > 0; o >>= 1) v += __shfl_xor_sync(0xffffffffu, v, o);
    if (lane == 0) sbuf[wid] = v;
    __syncthreads();
    if (wid == 0) {
        float r = (lane < 8) ? sbuf[lane] : 0.f;
        #pragma unroll
        for (int o = 4; o > 0; o >>= 1) r += __shfl_xor_sync(0xffffffffu, r, o);
        if (lane == 0) sbuf[0] = r;
    }
    __syncthreads();
    float r = sbuf[0];
    __syncthreads();
    return r;
}

// ---------------- residual + LN1 + softmax(fusion_w)-weighted sum ----------------
__global__ __launch_bounds__(256)
void ln1_fuse_kernel(const float* __restrict__ ATT, const float* __restrict__ ST,
                     const float* __restrict__ g1, const float* __restrict__ b1,
                     const float* __restrict__ fw, float* __restrict__ FUSED)
{
    __shared__ float sbuf[32];
    const int n = blockIdx.x, tid = threadIdx.x;

    float w[6];
    {
        float m = -1e30f;
        #pragma unroll
        for (int j = 0; j < 6; j++) { w[j] = fw[j]; m = fmaxf(m, w[j]); }
        float s = 0.f;
        #pragma unroll
        for (int j = 0; j < 6; j++) { w[j] = __expf(w[j] - m); s += w[j]; }
        float inv = 1.f / s;
        #pragma unroll
        for (int j = 0; j < 6; j++) w[j] *= inv;
    }

    float accv[4] = {0.f, 0.f, 0.f, 0.f};
    for (int j = 0; j < 6; j++) {
        size_t base = ((size_t)j * NTOK + n) * EDIM;
        float x[4], lsum = 0.f;
        #pragma unroll
        for (int tq = 0; tq < 4; tq++) {
            int e = tq * 256 + tid;
            x[tq] = ATT[base + e] + ST[base + e];
            lsum += x[tq];
        }
        float mean = block_sum(lsum, sbuf) * (1.f / EDIM);
        float lvar = 0.f;
        #pragma unroll
        for (int tq = 0; tq < 4; tq++) { float d = x[tq] - mean; lvar += d * d; }
        float var = block_sum(lvar, sbuf) * (1.f / EDIM);
        float inv = rsqrtf(var + LN_EPS);
        #pragma unroll
        for (int tq = 0; tq < 4; tq++) {
            int e = tq * 256 + tid;
            accv[tq] += w[j] * ((x[tq] - mean) * inv * g1[e] + b1[e]);
        }
    }
    #pragma unroll
    for (int tq = 0; tq < 4; tq++)
        FUSED[(size_t)n * EDIM + tq * 256 + tid] = accv[tq];
}

// ---------------- LeakyReLU + LN2 (in-place on d_out) ----------------
__global__ __launch_bounds__(256)
void lrelu_ln2_kernel(float* __restrict__ O, const float* __restrict__ g2,
                      const float* __restrict__ b2)
{
    __shared__ float sbuf[32];
    const int n = blockIdx.x, tid = threadIdx.x;
    size_t base = (size_t)n * HIDD;

    float x[4], lsum = 0.f;
    #pragma unroll
    for (int tq = 0; tq < 4; tq++) {
        int e = tq * 256 + tid;
        float v = O[base + e];
        v = (v >= 0.f) ? v : 0.01f * v;
        x[tq] = v; lsum += v;
    }
    float mean = block_sum(lsum, sbuf) * (1.f / HIDD);
    float lvar = 0.f;
    #pragma unroll
    for (int tq = 0; tq < 4; tq++) { float d = x[tq] - mean; lvar += d * d; }
    float var = block_sum(lvar, sbuf) * (1.f / HIDD);
    float inv = rsqrtf(var + LN_EPS);
    #pragma unroll
    for (int tq = 0; tq < 4; tq++) {
        int e = tq * 256 + tid;
        O[base + e] = (x[tq] - mean) * inv * g2[e] + b2[e];
    }
}

// ---------------- launch ----------------
extern "C" void kernel_launch(void* const* d_in, const int* in_sizes, int n_in,
                              void* d_out, int out_size)
{
    const float* st = (const float*)d_in[0];
    const float* Wq = (const float*)d_in[1];  const float* bq = (const float*)d_in[2];
    const float* Wk = (const float*)d_in[3];  const float* bk = (const float*)d_in[4];
    const float* Wv = (const float*)d_in[5];  const float* bv = (const float*)d_in[6];
    const float* Wo = (const float*)d_in[7];  const float* bo = (const float*)d_in[8];
    const float* g1 = (const float*)d_in[9];  const float* b1 = (const float*)d_in[10];
    const float* fw = (const float*)d_in[11];
    const float* Wf = (const float*)d_in[12]; const float* bf = (const float*)d_in[13];
    const float* g2 = (const float*)d_in[14]; const float* b2 = (const float*)d_in[15];
    float* out = (float*)d_out;

    float *Qb, *Kb, *Vb, *CTXb, *ATTb, *FUSb;
    cudaGetSymbolAddress((void**)&Qb,   g_Q);
    cudaGetSymbolAddress((void**)&Kb,   g_K);
    cudaGetSymbolAddress((void**)&Vb,   g_V);
    cudaGetSymbolAddress((void**)&CTXb, g_CTX);
    cudaGetSymbolAddress((void**)&ATTb, g_ATT);
    cudaGetSymbolAddress((void**)&FUSb, g_FUSED);

    dim3 blk(256);
    dim3 gproj(EDIM / 128, NROWS / 128);   // (8, 384)
    gemm_tf32<<<gproj, blk>>>(st, Wq, bq, Qb, NROWS, EDIM, EDIM);
    gemm_tf32<<<gproj, blk>>>(st, Wk, bk, Kb, NROWS, EDIM, EDIM);
    gemm_tf32<<<gproj, blk>>>(st, Wv, bv, Vb, NROWS, EDIM, EDIM);

    attn_kernel<<<NTOK, 256>>>(Qb, Kb, Vb, CTXb);

    gemm_tf32<<<gproj, blk>>>(CTXb, Wo, bo, ATTb, NROWS, EDIM, EDIM);

    ln1_fuse_kernel<<<NTOK, 256>>>(ATTb, st, g1, b1, fw, FUSb);

    dim3 gmlp(HIDD / 128, NTOK / 128);     // (8, 64)
    gemm_tf32<<<gmlp, blk>>>(FUSb, Wf, bf, out, NTOK, HIDD, EDIM);

    lrelu_ln2_kernel<<<NTOK, 256>>>(out, g2, b2);
}

// round 6
// speedup vs baseline: 5.6140x; 2.2813x over previous
#include <cuda_runtime.h>
#include <cuda_fp16.h>
#include <math.h>
#include <stdint.h>

// ---------------- problem constants ----------------
#define NTOK   8192          // B*S = 16*512
#define EDIM   1024
#define NHEAD  16
#define HDIM   64
#define NST    6
#define NROWS  (NST*NTOK)    // 49152
#define HIDD   1024
#define LN_EPS 1e-5f

// ---------------- scratch (device globals; no allocs allowed) ----------------
__device__ float  g_Q[(size_t)NROWS * EDIM];
__device__ float  g_K[(size_t)NROWS * EDIM];
__device__ float  g_V[(size_t)NROWS * EDIM];
__device__ float  g_ATT[(size_t)NROWS * EDIM];
__device__ __half g_STh[(size_t)NROWS * EDIM];
__device__ __half g_CTXh[(size_t)NROWS * EDIM];
__device__ __half g_FUSEDh[(size_t)NTOK * EDIM];
__device__ __half g_Wqh[(size_t)EDIM * EDIM];
__device__ __half g_Wkh[(size_t)EDIM * EDIM];
__device__ __half g_Wvh[(size_t)EDIM * EDIM];
__device__ __half g_Woh[(size_t)EDIM * EDIM];
__device__ __half g_Wfh[(size_t)HIDD * EDIM];

// ---------------- helpers ----------------
__device__ __forceinline__ uint32_t smem_u32(const void* p) {
    uint32_t a;
    asm("{ .reg .u64 t; cvta.to.shared.u64 t, %1; cvt.u32.u64 %0, t; }" : "=r"(a) : "l"(p));
    return a;
}

__device__ __forceinline__ void cp_async16(uint32_t dst, const void* src) {
    asm volatile("cp.async.cg.shared.global [%0], [%1], 16;"
                 :: "r"(dst), "l"(src) : "memory");
}

__device__ __forceinline__ void ldsm_x4(uint32_t* r, uint32_t addr) {
    asm volatile("ldmatrix.sync.aligned.m8n8.x4.shared.b16 {%0,%1,%2,%3}, [%4];"
                 : "=r"(r[0]), "=r"(r[1]), "=r"(r[2]), "=r"(r[3]) : "r"(addr));
}

__device__ __forceinline__ void mma_fp16(float* c, const uint32_t* a, const uint32_t* b) {
    asm volatile(
        "mma.sync.aligned.m16n8k16.row.col.f32.f16.f16.f32 "
        "{%0,%1,%2,%3}, {%4,%5,%6,%7}, {%8,%9}, {%0,%1,%2,%3};"
        : "+f"(c[0]), "+f"(c[1]), "+f"(c[2]), "+f"(c[3])
        : "r"(a[0]), "r"(a[1]), "r"(a[2]), "r"(a[3]), "r"(b[0]), "r"(b[1]));
}

__device__ __forceinline__ uint32_t sw128(uint32_t byte) {
    return byte ^ ((byte >> 3) & 0x70);
}

// ---------------- fp32 -> fp16 conversion (vectorized) ----------------
__global__ __launch_bounds__(256)
void f2h_kernel(const float4* __restrict__ src, uint2* __restrict__ dst, int n4)
{
    int i = blockIdx.x * blockDim.x + threadIdx.x;
    if (i < n4) {
        float4 v = src[i];
        __half2 lo = __floats2half2_rn(v.x, v.y);
        __half2 hi = __floats2half2_rn(v.z, v.w);
        dst[i] = make_uint2(*reinterpret_cast<uint32_t*>(&lo),
                            *reinterpret_cast<uint32_t*>(&hi));
    }
}

// ---------------- FP16 tensor-core GEMM ----------------
// C[M,Nc] = A[M,K] @ B[Nc,K]^T + bias[Nc], A/B fp16, C fp32.
// Block 128x128, BK=64 halves (128B rows, SW128), 256 threads = 8 warps (2x4),
// warp tile 64x32, double-buffered cp.async pipeline, ldmatrix fragments.
#define STG_BYTES 16384                      // 128 rows * 128 B
#define GEMMH_SMEM (1024 + 4 * STG_BYTES)    // align pad + 2 stages x (A+B)

extern __shared__ char dynsmem[];

__global__ __launch_bounds__(256)
void gemm_h(const __half* __restrict__ A, const __half* __restrict__ Bw,
            const float* __restrict__ bias, float* __restrict__ C,
            int M, int Nc, int Kd)
{
    const int tid  = threadIdx.x;
    const int warp = tid >> 5;
    const int lane = tid & 31;

    const int bm = blockIdx.y * 128;
    const int bn = blockIdx.x * 128;
    const int wm = (warp >> 2) * 64;
    const int wn = (warp & 3) * 32;

    uint32_t sbase = (smem_u32(dynsmem) + 1023u) & ~1023u;
    const uint32_t sA = sbase;                 // 2 x 16KB
    const uint32_t sB = sbase + 2 * STG_BYTES; // 2 x 16KB

    float acc[4][4][4];
    #pragma unroll
    for (int mt = 0; mt < 4; mt++)
        #pragma unroll
        for (int nt = 0; nt < 4; nt++)
            #pragma unroll
            for (int r = 0; r < 4; r++) acc[mt][nt][r] = 0.f;

    // cp.async mapping: 1024 16B-chunks per matrix per stage; 4 per thread.
    // chunk c: row = c>>3 (0..127), col16 = c&7.
    const int nstg = Kd / 64;

    // ldmatrix lane addressing (byte offsets within stage, pre-swizzled row base)
    // A (mt tile): row = wm + mt*16 + (lane&15), chunk16 = lane>>4
    const int a_row_in = lane & 15;
    const int a_ch     = lane >> 4;
    // B (nt2 tile): n = (lane&7) + ((lane>>4)&1)*8, chunk16 = (lane>>3)&1
    const int b_n_in = (lane & 7) + ((lane >> 4) & 1) * 8;
    const int b_ch   = (lane >> 3) & 1;

    auto load_stage = [&](int s, int buf) {
        const uint32_t da = sA + buf * STG_BYTES;
        const uint32_t db = sB + buf * STG_BYTES;
        #pragma unroll
        for (int i = 0; i < 4; i++) {
            int c = tid + i * 256;
            int row = c >> 3, col16 = c & 7;
            uint32_t sw = sw128(row * 128 + col16 * 16);
            const __half* ga = A  + (size_t)(bm + row) * Kd + s * 64 + col16 * 8;
            const __half* gb = Bw + (size_t)(bn + row) * Kd + s * 64 + col16 * 8;
            cp_async16(da + sw, ga);
            cp_async16(db + sw, gb);
        }
        asm volatile("cp.async.commit_group;" ::: "memory");
    };

    load_stage(0, 0);

    for (int s = 0; s < nstg; s++) {
        const int buf = s & 1;
        if (s + 1 < nstg) {
            load_stage(s + 1, buf ^ 1);
            asm volatile("cp.async.wait_group 1;" ::: "memory");
        } else {
            asm volatile("cp.async.wait_group 0;" ::: "memory");
        }
        __syncthreads();

        const uint32_t abuf = sA + buf * STG_BYTES;
        const uint32_t bbuf = sB + buf * STG_BYTES;

        #pragma unroll
        for (int ks = 0; ks < 4; ks++) {            // four k16 steps per stage
            uint32_t af[4][4], bfr[2][4];
            #pragma unroll
            for (int mt = 0; mt < 4; mt++) {
                uint32_t byte = (uint32_t)(wm + mt * 16 + a_row_in) * 128
                              + ks * 32 + a_ch * 16;
                ldsm_x4(af[mt], abuf + sw128(byte));
            }
            #pragma unroll
            for (int nt2 = 0; nt2 < 2; nt2++) {
                uint32_t byte = (uint32_t)(wn + nt2 * 16 + b_n_in) * 128
                              + ks * 32 + b_ch * 16;
                ldsm_x4(bfr[nt2], bbuf + sw128(byte));
            }
            #pragma unroll
            for (int mt = 0; mt < 4; mt++)
                #pragma unroll
                for (int nt = 0; nt < 4; nt++)
                    mma_fp16(acc[mt][nt], af[mt], &bfr[nt >> 1][(nt & 1) * 2]);
        }
        __syncthreads();
    }

    // epilogue: bias + store fp32
    const int g = lane >> 2;
    const int t = lane & 3;
    #pragma unroll
    for (int mt = 0; mt < 4; mt++) {
        int r = bm + wm + mt * 16 + g;
        #pragma unroll
        for (int nt = 0; nt < 4; nt++) {
            int cc = bn + wn + nt * 8 + 2 * t;
            float bi0 = bias[cc], bi1 = bias[cc + 1];
            float2 o0 = make_float2(acc[mt][nt][0] + bi0, acc[mt][nt][1] + bi1);
            float2 o1 = make_float2(acc[mt][nt][2] + bi0, acc[mt][nt][3] + bi1);
            *reinterpret_cast<float2*>(&C[(size_t)r * Nc + cc])       = o0;
            *reinterpret_cast<float2*>(&C[(size_t)(r + 8) * Nc + cc]) = o1;
        }
    }
}

// ---------------- tiny 6x6 attention per (token, head) ----------------
// reads fp32 Q/K/V, writes fp16 CTX (consumed by Wo GEMM)
__global__ __launch_bounds__(256)
void attn_kernel(const float* __restrict__ Q, const float* __restrict__ Kb,
                 const float* __restrict__ V, __half* __restrict__ CTX)
{
    const int n    = blockIdx.x;
    const int tid  = threadIdx.x;
    const int warp = tid >> 5;
    const int lane = tid & 31;

    __shared__ float sq[NST][512];
    __shared__ float sk[NST][512];
    __shared__ float sv[NST][512];
    __shared__ float ssc[8][40];

    for (int pass = 0; pass < 2; pass++) {
        const int coff = pass * 512;
        __syncthreads();
        for (int idx = tid; idx < NST * 512; idx += 256) {
            int j = idx >> 9, e = idx & 511;
            size_t gofs = ((size_t)j * NTOK + n) * EDIM + coff + e;
            sq[j][e] = Q[gofs];
            sk[j][e] = Kb[gofs];
            sv[j][e] = V[gofs];
        }
        __syncthreads();

        const int h  = pass * 8 + warp;
        const int lc = warp * HDIM;

        for (int p = lane; p < 36; p += 32) {
            int qi = p / 6, ki = p % 6;
            float s = 0.f;
            #pragma unroll
            for (int d = 0; d < HDIM; d++)
                s += sq[qi][lc + d] * sk[ki][lc + d];
            ssc[warp][p] = s * 0.125f;
        }
        __syncwarp();

        if (lane < 6) {
            float row[6], m = -1e30f;
            #pragma unroll
            for (int kk = 0; kk < 6; kk++) { row[kk] = ssc[warp][lane * 6 + kk]; m = fmaxf(m, row[kk]); }
            float s = 0.f;
            #pragma unroll
            for (int kk = 0; kk < 6; kk++) { row[kk] = __expf(row[kk] - m); s += row[kk]; }
            float inv = 1.f / s;
            #pragma unroll
            for (int kk = 0; kk < 6; kk++) ssc[warp][lane * 6 + kk] = row[kk] * inv;
        }
        __syncwarp();

        for (int o = lane; o < NST * HDIM; o += 32) {
            int qi = o >> 6, d = o & 63;
            float c = 0.f;
            #pragma unroll
            for (int kk = 0; kk < 6; kk++)
                c += ssc[warp][qi * 6 + kk] * sv[kk][lc + d];
            CTX[((size_t)qi * NTOK + n) * EDIM + h * HDIM + d] = __float2half_rn(c);
        }
    }
}

// ---------------- block reduction helper (256 threads) ----------------
__device__ __forceinline__ float block_sum(float v, float* sbuf)
{
    const int lane = threadIdx.x & 31;
    const int wid  = threadIdx.x >> 5;
    #pragma unroll
    for (int o = 16; o > 0; o >>= 1) v += __shfl_xor_sync(0xffffffffu, v, o);
    if (lane == 0) sbuf[wid] = v;
    __syncthreads();
    if (wid == 0) {
        float r = (lane < 8) ? sbuf[lane] : 0.f;
        #pragma unroll
        for (int o = 4; o > 0; o >>= 1) r += __shfl_xor_sync(0xffffffffu, r, o);
        if (lane == 0) sbuf[0] = r;
    }
    __syncthreads();
    float r = sbuf[0];
    __syncthreads();
    return r;
}

// ---------------- residual + LN1 + softmax(fusion_w)-weighted sum (-> fp16) ----------------
__global__ __launch_bounds__(256)
void ln1_fuse_kernel(const float* __restrict__ ATT, const float* __restrict__ ST,
                     const float* __restrict__ g1, const float* __restrict__ b1,
                     const float* __restrict__ fw, __half* __restrict__ FUSED)
{
    __shared__ float sbuf[32];
    const int n = blockIdx.x, tid = threadIdx.x;

    float w[6];
    {
        float m = -1e30f;
        #pragma unroll
        for (int j = 0; j < 6; j++) { w[j] = fw[j]; m = fmaxf(m, w[j]); }
        float s = 0.f;
        #pragma unroll
        for (int j = 0; j < 6; j++) { w[j] = __expf(w[j] - m); s += w[j]; }
        float inv = 1.f / s;
        #pragma unroll
        for (int j = 0; j < 6; j++) w[j] *= inv;
    }

    float accv[4] = {0.f, 0.f, 0.f, 0.f};
    for (int j = 0; j < 6; j++) {
        size_t base = ((size_t)j * NTOK + n) * EDIM;
        float x[4], lsum = 0.f;
        #pragma unroll
        for (int tq = 0; tq < 4; tq++) {
            int e = tq * 256 + tid;
            x[tq] = ATT[base + e] + ST[base + e];
            lsum += x[tq];
        }
        float mean = block_sum(lsum, sbuf) * (1.f / EDIM);
        float lvar = 0.f;
        #pragma unroll
        for (int tq = 0; tq < 4; tq++) { float d = x[tq] - mean; lvar += d * d; }
        float var = block_sum(lvar, sbuf) * (1.f / EDIM);
        float inv = rsqrtf(var + LN_EPS);
        #pragma unroll
        for (int tq = 0; tq < 4; tq++) {
            int e = tq * 256 + tid;
            accv[tq] += w[j] * ((x[tq] - mean) * inv * g1[e] + b1[e]);
        }
    }
    #pragma unroll
    for (int tq = 0; tq < 4; tq++)
        FUSED[(size_t)n * EDIM + tq * 256 + tid] = __float2half_rn(accv[tq]);
}

// ---------------- LeakyReLU + LN2 (in-place on d_out) ----------------
__global__ __launch_bounds__(256)
void lrelu_ln2_kernel(float* __restrict__ O, const float* __restrict__ g2,
                      const float* __restrict__ b2)
{
    __shared__ float sbuf[32];
    const int n = blockIdx.x, tid = threadIdx.x;
    size_t base = (size_t)n * HIDD;

    float x[4], lsum = 0.f;
    #pragma unroll
    for (int tq = 0; tq < 4; tq++) {
        int e = tq * 256 + tid;
        float v = O[base + e];
        v = (v >= 0.f) ? v : 0.01f * v;
        x[tq] = v; lsum += v;
    }
    float mean = block_sum(lsum, sbuf) * (1.f / HIDD);
    float lvar = 0.f;
    #pragma unroll
    for (int tq = 0; tq < 4; tq++) { float d = x[tq] - mean; lvar += d * d; }
    float var = block_sum(lvar, sbuf) * (1.f / HIDD);
    float inv = rsqrtf(var + LN_EPS);
    #pragma unroll
    for (int tq = 0; tq < 4; tq++) {
        int e = tq * 256 + tid;
        O[base + e] = (x[tq] - mean) * inv * g2[e] + b2[e];
    }
}

// ---------------- launch ----------------
extern "C" void kernel_launch(void* const* d_in, const int* in_sizes, int n_in,
                              void* d_out, int out_size)
{
    const float* st = (const float*)d_in[0];
    const float* Wq = (const float*)d_in[1];  const float* bq = (const float*)d_in[2];
    const float* Wk = (const float*)d_in[3];  const float* bk = (const float*)d_in[4];
    const float* Wv = (const float*)d_in[5];  const float* bv = (const float*)d_in[6];
    const float* Wo = (const float*)d_in[7];  const float* bo = (const float*)d_in[8];
    const float* g1 = (const float*)d_in[9];  const float* b1 = (const float*)d_in[10];
    const float* fw = (const float*)d_in[11];
    const float* Wf = (const float*)d_in[12]; const float* bf = (const float*)d_in[13];
    const float* g2 = (const float*)d_in[14]; const float* b2 = (const float*)d_in[15];
    float* out = (float*)d_out;

    float *Qb, *Kb, *Vb, *ATTb;
    __half *STh, *CTXh, *FUSh, *Wqh, *Wkh, *Wvh, *Woh, *Wfh;
    cudaGetSymbolAddress((void**)&Qb,   g_Q);
    cudaGetSymbolAddress((void**)&Kb,   g_K);
    cudaGetSymbolAddress((void**)&Vb,   g_V);
    cudaGetSymbolAddress((void**)&ATTb, g_ATT);
    cudaGetSymbolAddress((void**)&STh,  g_STh);
    cudaGetSymbolAddress((void**)&CTXh, g_CTXh);
    cudaGetSymbolAddress((void**)&FUSh, g_FUSEDh);
    cudaGetSymbolAddress((void**)&Wqh,  g_Wqh);
    cudaGetSymbolAddress((void**)&Wkh,  g_Wkh);
    cudaGetSymbolAddress((void**)&Wvh,  g_Wvh);
    cudaGetSymbolAddress((void**)&Woh,  g_Woh);
    cudaGetSymbolAddress((void**)&Wfh,  g_Wfh);

    cudaFuncSetAttribute(gemm_h, cudaFuncAttributeMaxDynamicSharedMemorySize,
                         GEMMH_SMEM);

    // ---- fp32 -> fp16 conversions ----
    {
        int n4 = (NROWS * EDIM) / 4;
        f2h_kernel<<<(n4 + 255) / 256, 256>>>((const float4*)st, (uint2*)STh, n4);
        int w4 = (EDIM * EDIM) / 4;
        f2h_kernel<<<(w4 + 255) / 256, 256>>>((const float4*)Wq, (uint2*)Wqh, w4);
        f2h_kernel<<<(w4 + 255) / 256, 256>>>((const float4*)Wk, (uint2*)Wkh, w4);
        f2h_kernel<<<(w4 + 255) / 256, 256>>>((const float4*)Wv, (uint2*)Wvh, w4);
        f2h_kernel<<<(w4 + 255) / 256, 256>>>((const float4*)Wo, (uint2*)Woh, w4);
        int f4 = (HIDD * EDIM) / 4;
        f2h_kernel<<<(f4 + 255) / 256, 256>>>((const float4*)Wf, (uint2*)Wfh, f4);
    }

    dim3 blk(256);
    dim3 gproj(EDIM / 128, NROWS / 128);   // (8, 384)
    gemm_h<<<gproj, blk, GEMMH_SMEM>>>(STh, Wqh, bq, Qb, NROWS, EDIM, EDIM);
    gemm_h<<<gproj, blk, GEMMH_SMEM>>>(STh, Wkh, bk, Kb, NROWS, EDIM, EDIM);
    gemm_h<<<gproj, blk, GEMMH_SMEM>>>(STh, Wvh, bv, Vb, NROWS, EDIM, EDIM);

    attn_kernel<<<NTOK, 256>>>(Qb, Kb, Vb, CTXh);

    gemm_h<<<gproj, blk, GEMMH_SMEM>>>(CTXh, Woh, bo, ATTb, NROWS, EDIM, EDIM);

    ln1_fuse_kernel<<<NTOK, 256>>>(ATTb, st, g1, b1, fw, FUSh);

    dim3 gmlp(HIDD / 128, NTOK / 128);     // (8, 64)
    gemm_h<<<gmlp, blk, GEMMH_SMEM>>>(FUSh, Wfh, bf, out, NTOK, HIDD, EDIM);

    lrelu_ln2_kernel<<<NTOK, 256>>>(out, g2, b2);
}